// round 6
// baseline (speedup 1.0000x reference)
#include <cuda_runtime.h>
#include <math.h>

// ---------------------------------------------------------------------------
// YOLOv1 loss — fused kernel: d^2 staging + chunk-granular scalar capture.
//
// Phase A streams 64 cells (5760 float pairs) via float4:
//   - every chunk: sd[i] = (p-t)^2  (branch-free, coalesced STS.128)
//   - the ~13% of chunks overlapping a cell's 10 scalar channels also
//     scatter raw values into ps[64*10] / ts[64*5] (predicated short path)
// Phase B: 64 threads compute IoU/coord/conf from ps/ts (LDS only).
// Phase C: class SSE = sum of precomputed d^2 for responsible cells (~5%).
// Block reduce -> global atomics -> last-block finalize (resets state).
//
// g_acc: 0 coord  1 conf  2 noobj1_num  3 n_noobj  4 sum(pc2^2)
//        5 n1     6 n2    7 cls1        8 cls2     9 nan flag
// ---------------------------------------------------------------------------

#define SGRID  14
#define NCLS   80
#define STRIDE 90
#define CELLS  64
#define GROUP_F (CELLS * STRIDE)        // 5760 floats
#define NBLOCKS 912                     // 152 SMs * 6 blocks
#define LAMBDA_COORD 5.0f
#define LAMBDA_NOOBJ 0.5f
#define EPS_IOU 1e-6f
#define EPS_WH  1e-8f

__device__ float        g_acc[10] = {0};
__device__ unsigned int g_count   = 0;

__device__ __forceinline__ float iou_img(float x1, float y1, float w1, float h1,
                                         float x2, float y2, float w2, float h2) {
    float ix0 = fmaxf(x1 - w1 * 0.5f, x2 - w2 * 0.5f);
    float iy0 = fmaxf(y1 - h1 * 0.5f, y2 - h2 * 0.5f);
    float ix1 = fminf(x1 + w1 * 0.5f, x2 + w2 * 0.5f);
    float iy1 = fminf(y1 + h1 * 0.5f, y2 + h2 * 0.5f);
    float inter = fmaxf(ix1 - ix0, 0.0f) * fmaxf(iy1 - iy0, 0.0f);
    float uni   = w1 * h1 + w2 * h2 - inter;
    return inter / (uni + EPS_IOU);
}

__global__ void __launch_bounds__(256, 6)
yolo_fused_kernel(const float* __restrict__ pred,
                  const float* __restrict__ targ,
                  float* __restrict__ out,
                  int ncells)
{
    __shared__ float sd[GROUP_F];        // (p-t)^2, linear
    __shared__ float ps[CELLS * 10];     // raw pred scalars
    __shared__ float ts[CELLS * 5];      // raw target scalars
    __shared__ float sm_m[CELLS];        // +1 resp1, -1 resp2, 0 none
    __shared__ int   s_list[CELLS];
    __shared__ int   s_cnt;
    __shared__ float sb[8][9];
    __shared__ unsigned int sn[8];
    __shared__ bool  is_last;

    const unsigned FULL = 0xffffffffu;
    const int tid  = threadIdx.x;
    const int lane = tid & 31;
    const int wib  = tid >> 5;
    const int ngroups = (ncells + CELLS - 1) / CELLS;

    float a[9];
#pragma unroll
    for (int i = 0; i < 9; i++) a[i] = 0.0f;
    unsigned int nanf = 0u;

    for (int g = blockIdx.x; g < ngroups; g += gridDim.x) {
        const int cbase = g * CELLS;
        const int cells = min(CELLS, ncells - cbase);
        const int nf    = cells * STRIDE;
        const int nv    = nf >> 2;

        // ---- Phase A: stream group ----
        const float4* pg = (const float4*)(pred + (size_t)cbase * STRIDE);
        const float4* tg = (const float4*)(targ + (size_t)cbase * STRIDE);
        if (tid == 0) s_cnt = 0;
#pragma unroll
        for (int k = 0; k < 6; k++) {
            int i2 = tid + k * 256;
            if (i2 < nv) {
                float4 v = pg[i2];
                float4 w = tg[i2];
                nanf |= (unsigned)((v.x != v.x) | (v.y != v.y) |
                                   (v.z != v.z) | (v.w != v.w) |
                                   (w.x != w.x) | (w.y != w.y) |
                                   (w.z != w.z) | (w.w != w.w));
                float4 d;
                d.x = (v.x - w.x) * (v.x - w.x);
                d.y = (v.y - w.y) * (v.y - w.y);
                d.z = (v.z - w.z) * (v.z - w.z);
                d.w = (v.w - w.w) * (v.w - w.w);
                ((float4*)sd)[i2] = d;

                // chunk-granular scalar capture (~13% of chunks)
                int idx  = i2 << 2;
                int cell = idx / STRIDE;            // mult-shift
                int ch   = idx - cell * STRIDE;     // even
                if (ch < 10 || ch >= 88) {
                    float pv[4] = {v.x, v.y, v.z, v.w};
                    float tv[4] = {w.x, w.y, w.z, w.w};
#pragma unroll
                    for (int j = 0; j < 4; j++) {
                        int chj = ch + j;
                        int cj  = cell;
                        if (chj >= STRIDE) { chj -= STRIDE; cj++; }
                        if (chj < 10) {
                            ps[cj * 10 + chj] = pv[j];
                            if (chj < 5) ts[cj * 5 + chj] = tv[j];
                        }
                    }
                }
            }
        }
        if (tid < (nf & 3)) {
            int i3 = (nv << 2) + tid;
            float v = (pred + (size_t)cbase * STRIDE)[i3];
            float w = (targ + (size_t)cbase * STRIDE)[i3];
            nanf |= (unsigned)((v != v) | (w != w));
            sd[i3] = (v - w) * (v - w);
            int cell = i3 / STRIDE;
            int ch   = i3 - cell * STRIDE;
            if (ch < 10) { ps[cell * 10 + ch] = v; if (ch < 5) ts[cell * 5 + ch] = w; }
        }
        __syncthreads();

        // ---- Phase B: per-cell scalars from smem ----
        if (tid < cells) {
            const int pb = tid * 10;
            const int tb = tid * 5;
            float px1 = ps[pb + 0], py1 = ps[pb + 1];
            float pw1 = ps[pb + 2], ph1 = ps[pb + 3];
            float pc1 = ps[pb + 4];
            float px2 = ps[pb + 5], py2 = ps[pb + 6];
            float pw2 = ps[pb + 7], ph2 = ps[pb + 8];
            float pc2 = ps[pb + 9];
            float tx  = ts[tb + 0], ty = ts[tb + 1];
            float tw  = ts[tb + 2], th = ts[tb + 3];
            float tcf = ts[tb + 4];

            int gc = cbase + tid;
            float cx = (float)(gc % SGRID);
            float cy = (float)((gc / SGRID) % SGRID);

            const float invS = 1.0f / (float)SGRID;
            float X1 = (cx + px1) * invS, Y1 = (cy + py1) * invS;
            float X2 = (cx + px2) * invS, Y2 = (cy + py2) * invS;
            float TX = (cx + tx ) * invS, TY = (cy + ty ) * invS;

            float iou1 = iou_img(X1, Y1, pw1, ph1, TX, TY, tw, th);
            float iou2 = iou_img(X2, Y2, pw2, ph2, TX, TY, tw, th);

            bool obj   = (tcf == 1.0f);
            bool noobj = (tcf == 0.0f);

            a[4] += pc2 * pc2;
            if (noobj) { a[2] += pc1 * pc1; a[3] += 1.0f; }

            float m = 0.0f;
            if (obj) {
                bool r1 = (iou1 >= iou2);
                m = r1 ? 1.0f : -1.0f;
                float sw1 = sqrtf(fmaxf(pw1, EPS_WH)) - sqrtf(fmaxf(tw, EPS_WH));
                float sh1 = sqrtf(fmaxf(ph1, EPS_WH)) - sqrtf(fmaxf(th, EPS_WH));
                float sw2 = sqrtf(fmaxf(pw2, EPS_WH)) - sqrtf(fmaxf(tw, EPS_WH));
                float sh2 = sqrtf(fmaxf(ph2, EPS_WH)) - sqrtf(fmaxf(th, EPS_WH));
                float c1 = (px1 - tx) * (px1 - tx) + (py1 - ty) * (py1 - ty)
                         + sw1 * sw1 + sh1 * sh1;
                float c2 = (px2 - tx) * (px2 - tx) + (py2 - ty) * (py2 - ty)
                         + sw2 * sw2 + sh2 * sh2;
                float e1 = pc1 - iou1;
                float e2 = pc2 - iou2;
                if (r1) {
                    a[0] += c1;
                    a[1] += e1 * e1 + pc2 * pc2;
                    a[5] += 1.0f;
                } else {
                    a[0] += c2;
                    a[1] += e2 * e2 + pc1 * pc1;
                    a[6] += 1.0f;
                }
                int pos = atomicAdd(&s_cnt, 1);
                s_list[pos] = tid;
            }
            sm_m[tid] = m;
        }
        __syncthreads();

        // ---- Phase C: class SSE from precomputed d^2 ----
        const int tot = s_cnt * NCLS;
        for (int e = tid; e < tot; e += 256) {
            int k = e / NCLS;
            int j = e - k * NCLS;
            int i = s_list[k];
            float dd = sd[i * STRIDE + 10 + j];
            if (sm_m[i] > 0.0f) a[7] += dd; else a[8] += dd;
        }
        __syncthreads();
    }

    // ---- warp reduction ----
#pragma unroll
    for (int i = 0; i < 9; i++) {
        float v = a[i];
#pragma unroll
        for (int o = 16; o > 0; o >>= 1) v += __shfl_down_sync(FULL, v, o);
        a[i] = v;
    }
    unsigned int nanw = __any_sync(FULL, nanf != 0u) ? 1u : 0u;

    // ---- block reduction -> global atomics ----
    if (lane == 0) {
#pragma unroll
        for (int i = 0; i < 9; i++) sb[wib][i] = a[i];
        sn[wib] = nanw;
    }
    __syncthreads();
    if (tid < 9) {
        float v = 0.0f;
#pragma unroll
        for (int w = 0; w < 8; w++) v += sb[w][tid];
        atomicAdd(&g_acc[tid], v);
    }
    if (tid == 9) {
        unsigned int v = 0u;
#pragma unroll
        for (int w = 0; w < 8; w++) v |= sn[w];
        if (v) atomicAdd(&g_acc[9], 1.0f);
    }

    // ---- last-block finalize ----
    __threadfence();
    __syncthreads();
    if (tid == 0) {
        unsigned int old = atomicAdd(&g_count, 1u);
        is_last = (old == (unsigned int)(gridDim.x - 1));
    }
    __syncthreads();
    if (is_last && tid == 0) {
        __threadfence();
        volatile float* ga = g_acc;
        float coord   = LAMBDA_COORD * ga[0];
        float conf    = ga[1];
        float n_noobj = ga[3];
        float noobj1  = ga[2] / fmaxf(n_noobj, 1.0f);
        float noobj2  = ga[4] / (float)ncells;
        if (n_noobj > 0.0f) conf += LAMBDA_NOOBJ * (noobj1 + noobj2);
        float n1 = ga[5], n2 = ga[6];
        float cls_loss = 0.0f;
        if (n1 > 0.0f) cls_loss += ga[7] / fmaxf(n1 * (float)NCLS, 1.0f);
        if (n2 > 0.0f) cls_loss += ga[8] / fmaxf(n2 * (float)NCLS, 1.0f);
        float B = (float)ncells / (float)(SGRID * SGRID);
        float total = (coord + conf + cls_loss) / B;
        out[0] = (ga[9] != 0.0f) ? 0.0f : total;

#pragma unroll
        for (int i = 0; i < 10; i++) g_acc[i] = 0.0f;
        g_count = 0u;
    }
}

extern "C" void kernel_launch(void* const* d_in, const int* in_sizes, int n_in,
                              void* d_out, int out_size) {
    const float* pred = (const float*)d_in[0];
    const float* targ = (const float*)d_in[1];
    float* out = (float*)d_out;

    int total_elems = in_sizes[0];
    int ncells = total_elems / STRIDE;

    yolo_fused_kernel<<<NBLOCKS, 256>>>(pred, targ, out, ncells);
}

// round 7
// speedup vs baseline: 3.2095x; 3.2095x over previous
#include <cuda_runtime.h>
#include <math.h>

// ---------------------------------------------------------------------------
// YOLOv1 loss — fused kernel: pristine d^2 streaming + separate scalar pass.
//
// Phase A1: stream 64 cells (1440 float4 pairs): sd[i]=(p-t)^2.
//           Loop body is EXACTLY load/load/fma/store — no branches, no
//           division — so ptxas front-batches the LDG.128s (high MLP).
// Phase A2: (still pre-barrier) 512 float2 loads re-fetch the 15 scalar
//           channels per cell from global into ps/ts. These overlap A1's
//           in-flight loads (L1/MSHR hits), costing no extra DRAM time.
// Phase B:  64 threads compute IoU/coord/conf from ps/ts (smem only).
// Phase C:  class SSE = sum of precomputed d^2 for responsible cells (~5%).
// Block reduce -> global atomics -> last-block finalize (resets state so
// graph replays are deterministic).
//
// g_acc: 0 coord  1 conf  2 noobj1_num  3 n_noobj  4 sum(pc2^2)
//        5 n1     6 n2    7 cls1        8 cls2     9 nan flag
// ---------------------------------------------------------------------------

#define SGRID  14
#define NCLS   80
#define STRIDE 90
#define CELLS  64
#define GROUP_F (CELLS * STRIDE)        // 5760 floats
#define NBLOCKS 912                     // 152 SMs * 6 blocks
#define LAMBDA_COORD 5.0f
#define LAMBDA_NOOBJ 0.5f
#define EPS_IOU 1e-6f
#define EPS_WH  1e-8f

__device__ float        g_acc[10] = {0};
__device__ unsigned int g_count   = 0;

__device__ __forceinline__ float iou_img(float x1, float y1, float w1, float h1,
                                         float x2, float y2, float w2, float h2) {
    float ix0 = fmaxf(x1 - w1 * 0.5f, x2 - w2 * 0.5f);
    float iy0 = fmaxf(y1 - h1 * 0.5f, y2 - h2 * 0.5f);
    float ix1 = fminf(x1 + w1 * 0.5f, x2 + w2 * 0.5f);
    float iy1 = fminf(y1 + h1 * 0.5f, y2 + h2 * 0.5f);
    float inter = fmaxf(ix1 - ix0, 0.0f) * fmaxf(iy1 - iy0, 0.0f);
    float uni   = w1 * h1 + w2 * h2 - inter;
    return inter / (uni + EPS_IOU);
}

__global__ void __launch_bounds__(256, 6)
yolo_fused_kernel(const float* __restrict__ pred,
                  const float* __restrict__ targ,
                  float* __restrict__ out,
                  int ncells)
{
    __shared__ float sd[GROUP_F];        // (p-t)^2, linear
    __shared__ float ps[CELLS * 10];     // raw pred scalars (ch 0..9)
    __shared__ float ts[CELLS * 6];      // raw target scalars (ch 0..5; 5 unused)
    __shared__ float sm_m[CELLS];        // +1 resp1, -1 resp2, 0 none
    __shared__ int   s_list[CELLS];
    __shared__ int   s_cnt;
    __shared__ float sb[8][9];
    __shared__ unsigned int sn[8];
    __shared__ bool  is_last;

    const unsigned FULL = 0xffffffffu;
    const int tid  = threadIdx.x;
    const int lane = tid & 31;
    const int wib  = tid >> 5;
    const int ngroups = (ncells + CELLS - 1) / CELLS;

    float a[9];
#pragma unroll
    for (int i = 0; i < 9; i++) a[i] = 0.0f;
    unsigned int nanf = 0u;

    for (int g = blockIdx.x; g < ngroups; g += gridDim.x) {
        const int cbase = g * CELLS;
        const int cells = min(CELLS, ncells - cbase);
        const int nf    = cells * STRIDE;
        const int nv    = nf >> 2;

        const float* pbase = pred + (size_t)cbase * STRIDE;
        const float* tbase = targ + (size_t)cbase * STRIDE;

        if (tid == 0) s_cnt = 0;

        // ---- Phase A1: pristine streaming (NO branches in body) ----
        const float4* pg = (const float4*)pbase;
        const float4* tg = (const float4*)tbase;
#pragma unroll
        for (int k = 0; k < 6; k++) {
            int i2 = tid + k * 256;
            if (i2 < nv) {
                float4 v = pg[i2];
                float4 w = tg[i2];
                nanf |= (unsigned)((v.x != v.x) | (v.y != v.y) |
                                   (v.z != v.z) | (v.w != v.w) |
                                   (w.x != w.x) | (w.y != w.y) |
                                   (w.z != w.z) | (w.w != w.w));
                float4 d;
                d.x = (v.x - w.x) * (v.x - w.x);
                d.y = (v.y - w.y) * (v.y - w.y);
                d.z = (v.z - w.z) * (v.z - w.z);
                d.w = (v.w - w.w) * (v.w - w.w);
                ((float4*)sd)[i2] = d;
            }
        }
        if (tid < (nf & 3)) {
            int i3 = (nv << 2) + tid;
            float v = pbase[i3];
            float w = tbase[i3];
            nanf |= (unsigned)((v != v) | (w != w));
            sd[i3] = (v - w) * (v - w);
        }

        // ---- Phase A2: scalar capture (pre-barrier; overlaps A1 loads) ----
        // 320 pred float2 (5 per cell: ch 0..9) + 192 targ float2 (3 per
        // cell: ch 0..5) = 512 loads, 2 per thread.
#pragma unroll
        for (int e0 = 0; e0 < 2; e0++) {
            int e = tid + e0 * 256;
            if (e < 320) {
                int cell = e / 5;           // mult-shift
                int j    = e - cell * 5;    // 0..4
                if (cell < cells) {
                    float2 pv = *(const float2*)(pbase + cell * STRIDE + 2 * j);
                    ps[cell * 10 + 2 * j + 0] = pv.x;
                    ps[cell * 10 + 2 * j + 1] = pv.y;
                }
            } else {
                int u    = e - 320;
                int cell = u / 3;
                int j    = u - cell * 3;    // 0..2
                if (cell < cells) {
                    float2 tv = *(const float2*)(tbase + cell * STRIDE + 2 * j);
                    ts[cell * 6 + 2 * j + 0] = tv.x;
                    ts[cell * 6 + 2 * j + 1] = tv.y;
                }
            }
        }
        __syncthreads();

        // ---- Phase B: per-cell scalars from smem ----
        if (tid < cells) {
            const int pb = tid * 10;
            const int tb = tid * 6;
            float px1 = ps[pb + 0], py1 = ps[pb + 1];
            float pw1 = ps[pb + 2], ph1 = ps[pb + 3];
            float pc1 = ps[pb + 4];
            float px2 = ps[pb + 5], py2 = ps[pb + 6];
            float pw2 = ps[pb + 7], ph2 = ps[pb + 8];
            float pc2 = ps[pb + 9];
            float tx  = ts[tb + 0], ty = ts[tb + 1];
            float tw  = ts[tb + 2], th = ts[tb + 3];
            float tcf = ts[tb + 4];

            int gc = cbase + tid;
            float cx = (float)(gc % SGRID);
            float cy = (float)((gc / SGRID) % SGRID);

            const float invS = 1.0f / (float)SGRID;
            float X1 = (cx + px1) * invS, Y1 = (cy + py1) * invS;
            float X2 = (cx + px2) * invS, Y2 = (cy + py2) * invS;
            float TX = (cx + tx ) * invS, TY = (cy + ty ) * invS;

            float iou1 = iou_img(X1, Y1, pw1, ph1, TX, TY, tw, th);
            float iou2 = iou_img(X2, Y2, pw2, ph2, TX, TY, tw, th);

            bool obj   = (tcf == 1.0f);
            bool noobj = (tcf == 0.0f);

            a[4] += pc2 * pc2;
            if (noobj) { a[2] += pc1 * pc1; a[3] += 1.0f; }

            float m = 0.0f;
            if (obj) {
                bool r1 = (iou1 >= iou2);
                m = r1 ? 1.0f : -1.0f;
                float sw1 = sqrtf(fmaxf(pw1, EPS_WH)) - sqrtf(fmaxf(tw, EPS_WH));
                float sh1 = sqrtf(fmaxf(ph1, EPS_WH)) - sqrtf(fmaxf(th, EPS_WH));
                float sw2 = sqrtf(fmaxf(pw2, EPS_WH)) - sqrtf(fmaxf(tw, EPS_WH));
                float sh2 = sqrtf(fmaxf(ph2, EPS_WH)) - sqrtf(fmaxf(th, EPS_WH));
                float c1 = (px1 - tx) * (px1 - tx) + (py1 - ty) * (py1 - ty)
                         + sw1 * sw1 + sh1 * sh1;
                float c2 = (px2 - tx) * (px2 - tx) + (py2 - ty) * (py2 - ty)
                         + sw2 * sw2 + sh2 * sh2;
                float e1 = pc1 - iou1;
                float e2 = pc2 - iou2;
                if (r1) {
                    a[0] += c1;
                    a[1] += e1 * e1 + pc2 * pc2;
                    a[5] += 1.0f;
                } else {
                    a[0] += c2;
                    a[1] += e2 * e2 + pc1 * pc1;
                    a[6] += 1.0f;
                }
                int pos = atomicAdd(&s_cnt, 1);
                s_list[pos] = tid;
            }
            sm_m[tid] = m;
        }
        __syncthreads();

        // ---- Phase C: class SSE from precomputed d^2 ----
        const int tot = s_cnt * NCLS;
        for (int e = tid; e < tot; e += 256) {
            int k = e / NCLS;
            int j = e - k * NCLS;
            int i = s_list[k];
            float dd = sd[i * STRIDE + 10 + j];
            if (sm_m[i] > 0.0f) a[7] += dd; else a[8] += dd;
        }
        __syncthreads();
    }

    // ---- warp reduction ----
#pragma unroll
    for (int i = 0; i < 9; i++) {
        float v = a[i];
#pragma unroll
        for (int o = 16; o > 0; o >>= 1) v += __shfl_down_sync(FULL, v, o);
        a[i] = v;
    }
    unsigned int nanw = __any_sync(FULL, nanf != 0u) ? 1u : 0u;

    // ---- block reduction -> global atomics ----
    if (lane == 0) {
#pragma unroll
        for (int i = 0; i < 9; i++) sb[wib][i] = a[i];
        sn[wib] = nanw;
    }
    __syncthreads();
    if (tid < 9) {
        float v = 0.0f;
#pragma unroll
        for (int w = 0; w < 8; w++) v += sb[w][tid];
        atomicAdd(&g_acc[tid], v);
    }
    if (tid == 9) {
        unsigned int v = 0u;
#pragma unroll
        for (int w = 0; w < 8; w++) v |= sn[w];
        if (v) atomicAdd(&g_acc[9], 1.0f);
    }

    // ---- last-block finalize ----
    __threadfence();
    __syncthreads();
    if (tid == 0) {
        unsigned int old = atomicAdd(&g_count, 1u);
        is_last = (old == (unsigned int)(gridDim.x - 1));
    }
    __syncthreads();
    if (is_last && tid == 0) {
        __threadfence();
        volatile float* ga = g_acc;
        float coord   = LAMBDA_COORD * ga[0];
        float conf    = ga[1];
        float n_noobj = ga[3];
        float noobj1  = ga[2] / fmaxf(n_noobj, 1.0f);
        float noobj2  = ga[4] / (float)ncells;
        if (n_noobj > 0.0f) conf += LAMBDA_NOOBJ * (noobj1 + noobj2);
        float n1 = ga[5], n2 = ga[6];
        float cls_loss = 0.0f;
        if (n1 > 0.0f) cls_loss += ga[7] / fmaxf(n1 * (float)NCLS, 1.0f);
        if (n2 > 0.0f) cls_loss += ga[8] / fmaxf(n2 * (float)NCLS, 1.0f);
        float B = (float)ncells / (float)(SGRID * SGRID);
        float total = (coord + conf + cls_loss) / B;
        out[0] = (ga[9] != 0.0f) ? 0.0f : total;

#pragma unroll
        for (int i = 0; i < 10; i++) g_acc[i] = 0.0f;
        g_count = 0u;
    }
}

extern "C" void kernel_launch(void* const* d_in, const int* in_sizes, int n_in,
                              void* d_out, int out_size) {
    const float* pred = (const float*)d_in[0];
    const float* targ = (const float*)d_in[1];
    float* out = (float*)d_out;

    int total_elems = in_sizes[0];
    int ncells = total_elems / STRIDE;

    yolo_fused_kernel<<<NBLOCKS, 256>>>(pred, targ, out, ncells);
}

// round 8
// speedup vs baseline: 4.0807x; 1.2715x over previous
#include <cuda_runtime.h>
#include <math.h>
#include <stdint.h>

// ---------------------------------------------------------------------------
// YOLOv1 loss — cp.async double-buffered pipeline.
//
// Per block, groups of 32 cells, grid-strided:
//   fill(g+stride -> buf^1) via cp.async.cg (no dest regs -> MLP not
//   reg-limited); wait_group 1 drains fill(g); consume buf:
//     - NaN scan (float4 LDS over everything)
//     - Phase B: warp 0, thread i = cell i: IoU/coord/conf; responsible
//       cells also sum their 80-class SSE inline (40 x float2 diffs).
// DRAM stream is continuous across the consume barriers.
//
// g_acc: 0 coord  1 conf  2 noobj1_num  3 n_noobj  4 sum(pc2^2)
//        5 n1     6 n2    7 cls1        8 cls2     9 nan flag
// ---------------------------------------------------------------------------

#define SGRID  14
#define NCLS   80
#define STRIDE 90
#define CELLS  32
#define GF     (CELLS * STRIDE)       // 2880 floats per tensor per group
#define NBLOCKS 608                   // 152 SMs * 4 blocks
#define LAMBDA_COORD 5.0f
#define LAMBDA_NOOBJ 0.5f
#define EPS_IOU 1e-6f
#define EPS_WH  1e-8f

__device__ float        g_acc[10] = {0};
__device__ unsigned int g_count   = 0;

__device__ __forceinline__ void cp_async16(float* dst, const float* src) {
    uint32_t s = (uint32_t)__cvta_generic_to_shared(dst);
    asm volatile("cp.async.cg.shared.global [%0], [%1], 16;" :: "r"(s), "l"(src));
}
__device__ __forceinline__ void cp_commit() {
    asm volatile("cp.async.commit_group;");
}
__device__ __forceinline__ void cp_wait1() {
    asm volatile("cp.async.wait_group 1;");
}

__device__ __forceinline__ float iou_img(float x1, float y1, float w1, float h1,
                                         float x2, float y2, float w2, float h2) {
    float ix0 = fmaxf(x1 - w1 * 0.5f, x2 - w2 * 0.5f);
    float iy0 = fmaxf(y1 - h1 * 0.5f, y2 - h2 * 0.5f);
    float ix1 = fminf(x1 + w1 * 0.5f, x2 + w2 * 0.5f);
    float iy1 = fminf(y1 + h1 * 0.5f, y2 + h2 * 0.5f);
    float inter = fmaxf(ix1 - ix0, 0.0f) * fmaxf(iy1 - iy0, 0.0f);
    float uni   = w1 * h1 + w2 * h2 - inter;
    return inter / (uni + EPS_IOU);
}

// issue async fill of one group's raw data into (dp, dt)
__device__ __forceinline__ void fill_group(const float* __restrict__ pb,
                                           const float* __restrict__ tb,
                                           float* dp, float* dt,
                                           int nf, int tid) {
    int nv = nf >> 2;                 // float4 count (720 for full group)
#pragma unroll
    for (int k = 0; k < 3; k++) {
        int i = tid + k * 256;
        if (i < nv) {
            cp_async16(dp + 4 * i, pb + 4 * i);
            cp_async16(dt + 4 * i, tb + 4 * i);
        }
    }
    if (tid < (nf & 3)) {             // rare scalar tail (plain ld/st)
        int i3 = (nv << 2) + tid;
        dp[i3] = pb[i3];
        dt[i3] = tb[i3];
    }
}

__global__ void __launch_bounds__(256, 4)
yolo_fused_kernel(const float* __restrict__ pred,
                  const float* __restrict__ targ,
                  float* __restrict__ out,
                  int ncells)
{
    __shared__ __align__(16) float sp[2][GF];
    __shared__ __align__(16) float st[2][GF];
    __shared__ float sb[8][9];
    __shared__ unsigned int sn[8];
    __shared__ bool  is_last;

    const unsigned FULL = 0xffffffffu;
    const int tid  = threadIdx.x;
    const int lane = tid & 31;
    const int wib  = tid >> 5;
    const int gstride = gridDim.x;
    const int ngroups = (ncells + CELLS - 1) / CELLS;

    float a[9];
#pragma unroll
    for (int i = 0; i < 9; i++) a[i] = 0.0f;
    unsigned int nanf = 0u;

    // ---- prologue: fill first group into buffer 0 ----
    int g0 = blockIdx.x;
    if (g0 < ngroups) {
        int cbase = g0 * CELLS;
        int nf = min(CELLS, ncells - cbase) * STRIDE;
        fill_group(pred + (size_t)cbase * STRIDE, targ + (size_t)cbase * STRIDE,
                   sp[0], st[0], nf, tid);
    }
    cp_commit();

    int b = 0;
    for (int g = g0; g < ngroups; g += gstride) {
        // ---- issue next fill into the other buffer ----
        int gn = g + gstride;
        if (gn < ngroups) {
            int cb2 = gn * CELLS;
            int nf2 = min(CELLS, ncells - cb2) * STRIDE;
            fill_group(pred + (size_t)cb2 * STRIDE, targ + (size_t)cb2 * STRIDE,
                       sp[b ^ 1], st[b ^ 1], nf2, tid);
        }
        cp_commit();
        cp_wait1();              // fill(g) complete; fill(gn) may remain in flight
        __syncthreads();

        const int cbase = g * CELLS;
        const int cells = min(CELLS, ncells - cbase);
        const int nf    = cells * STRIDE;
        const int nv    = nf >> 2;
        const float* cpb = sp[b];
        const float* ctb = st[b];

        // ---- NaN scan (full data, float4 LDS) ----
#pragma unroll
        for (int k = 0; k < 3; k++) {
            int i = tid + k * 256;
            if (i < nv) {
                float4 v = ((const float4*)cpb)[i];
                float4 w = ((const float4*)ctb)[i];
                nanf |= (unsigned)((v.x != v.x) | (v.y != v.y) |
                                   (v.z != v.z) | (v.w != v.w) |
                                   (w.x != w.x) | (w.y != w.y) |
                                   (w.z != w.z) | (w.w != w.w));
            }
        }
        if (tid < (nf & 3)) {
            int i3 = (nv << 2) + tid;
            float v = cpb[i3], w = ctb[i3];
            nanf |= (unsigned)((v != v) | (w != w));
        }

        // ---- Phase B (+ fused class SSE): one thread per cell ----
        if (tid < cells) {
            const float* p = cpb + tid * STRIDE;
            const float* t = ctb + tid * STRIDE;
            float px1 = p[0], py1 = p[1], pw1 = p[2], ph1 = p[3], pc1 = p[4];
            float px2 = p[5], py2 = p[6], pw2 = p[7], ph2 = p[8], pc2 = p[9];
            float tx  = t[0], ty  = t[1], tw  = t[2], th  = t[3], tcf = t[4];

            int gc = cbase + tid;
            float cx = (float)(gc % SGRID);
            float cy = (float)((gc / SGRID) % SGRID);

            const float invS = 1.0f / (float)SGRID;
            float X1 = (cx + px1) * invS, Y1 = (cy + py1) * invS;
            float X2 = (cx + px2) * invS, Y2 = (cy + py2) * invS;
            float TX = (cx + tx ) * invS, TY = (cy + ty ) * invS;

            float iou1 = iou_img(X1, Y1, pw1, ph1, TX, TY, tw, th);
            float iou2 = iou_img(X2, Y2, pw2, ph2, TX, TY, tw, th);

            bool obj   = (tcf == 1.0f);
            bool noobj = (tcf == 0.0f);

            a[4] += pc2 * pc2;
            if (noobj) { a[2] += pc1 * pc1; a[3] += 1.0f; }

            if (obj) {
                bool r1 = (iou1 >= iou2);
                float sw1 = sqrtf(fmaxf(pw1, EPS_WH)) - sqrtf(fmaxf(tw, EPS_WH));
                float sh1 = sqrtf(fmaxf(ph1, EPS_WH)) - sqrtf(fmaxf(th, EPS_WH));
                float sw2 = sqrtf(fmaxf(pw2, EPS_WH)) - sqrtf(fmaxf(tw, EPS_WH));
                float sh2 = sqrtf(fmaxf(ph2, EPS_WH)) - sqrtf(fmaxf(th, EPS_WH));
                float c1 = (px1 - tx) * (px1 - tx) + (py1 - ty) * (py1 - ty)
                         + sw1 * sw1 + sh1 * sh1;
                float c2 = (px2 - tx) * (px2 - tx) + (py2 - ty) * (py2 - ty)
                         + sw2 * sw2 + sh2 * sh2;
                float e1 = pc1 - iou1;
                float e2 = pc2 - iou2;
                if (r1) {
                    a[0] += c1;
                    a[1] += e1 * e1 + pc2 * pc2;
                    a[5] += 1.0f;
                } else {
                    a[0] += c2;
                    a[1] += e2 * e2 + pc1 * pc1;
                    a[6] += 1.0f;
                }
                // fused class SSE: channels 10..89 as 40 float2 diffs
                float s = 0.0f;
                const float2* pc2p = (const float2*)(p + 10);
                const float2* tc2p = (const float2*)(t + 10);
#pragma unroll 8
                for (int j = 0; j < 40; j++) {
                    float2 pv = pc2p[j], tv = tc2p[j];
                    float dx = pv.x - tv.x;
                    float dy = pv.y - tv.y;
                    s += dx * dx + dy * dy;
                }
                if (r1) a[7] += s; else a[8] += s;
            }
        }
        __syncthreads();         // buf b free for refill next iteration
        b ^= 1;
    }

    // ---- warp reduction ----
#pragma unroll
    for (int i = 0; i < 9; i++) {
        float v = a[i];
#pragma unroll
        for (int o = 16; o > 0; o >>= 1) v += __shfl_down_sync(FULL, v, o);
        a[i] = v;
    }
    unsigned int nanw = __any_sync(FULL, nanf != 0u) ? 1u : 0u;

    // ---- block reduction -> global atomics ----
    if (lane == 0) {
#pragma unroll
        for (int i = 0; i < 9; i++) sb[wib][i] = a[i];
        sn[wib] = nanw;
    }
    __syncthreads();
    if (tid < 9) {
        float v = 0.0f;
#pragma unroll
        for (int w = 0; w < 8; w++) v += sb[w][tid];
        atomicAdd(&g_acc[tid], v);
    }
    if (tid == 9) {
        unsigned int v = 0u;
#pragma unroll
        for (int w = 0; w < 8; w++) v |= sn[w];
        if (v) atomicAdd(&g_acc[9], 1.0f);
    }

    // ---- last-block finalize ----
    __threadfence();
    __syncthreads();
    if (tid == 0) {
        unsigned int old = atomicAdd(&g_count, 1u);
        is_last = (old == (unsigned int)(gridDim.x - 1));
    }
    __syncthreads();
    if (is_last && tid == 0) {
        __threadfence();
        volatile float* ga = g_acc;
        float coord   = LAMBDA_COORD * ga[0];
        float conf    = ga[1];
        float n_noobj = ga[3];
        float noobj1  = ga[2] / fmaxf(n_noobj, 1.0f);
        float noobj2  = ga[4] / (float)ncells;
        if (n_noobj > 0.0f) conf += LAMBDA_NOOBJ * (noobj1 + noobj2);
        float n1 = ga[5], n2 = ga[6];
        float cls_loss = 0.0f;
        if (n1 > 0.0f) cls_loss += ga[7] / fmaxf(n1 * (float)NCLS, 1.0f);
        if (n2 > 0.0f) cls_loss += ga[8] / fmaxf(n2 * (float)NCLS, 1.0f);
        float B = (float)ncells / (float)(SGRID * SGRID);
        float total = (coord + conf + cls_loss) / B;
        out[0] = (ga[9] != 0.0f) ? 0.0f : total;

#pragma unroll
        for (int i = 0; i < 10; i++) g_acc[i] = 0.0f;
        g_count = 0u;
    }
}

extern "C" void kernel_launch(void* const* d_in, const int* in_sizes, int n_in,
                              void* d_out, int out_size) {
    const float* pred = (const float*)d_in[0];
    const float* targ = (const float*)d_in[1];
    float* out = (float*)d_out;

    int total_elems = in_sizes[0];
    int ncells = total_elems / STRIDE;

    yolo_fused_kernel<<<NBLOCKS, 256>>>(pred, targ, out, ncells);
}